// round 5
// baseline (speedup 1.0000x reference)
#include <cuda_runtime.h>
#include <math.h>

// ---------------- problem constants (fixed shapes) ----------------
#define M_BOXES 512
#define N_IMGS  2
#define C_FEAT  512
#define POOLSZ  14
#define SP      196            // 14*14
#define HID     1024
#define NCLS    81
#define OCONV   256
#define KFC     100352         // C_FEAT*SP
#define KCONV   4608           // C_FEAT*9
#define SPLITK  8
#define KSLICE  (KFC/SPLITK)   // 12544
#define PART    (M_BOXES*NCLS) // 41472 (output section size)
#define MROWS   (M_BOXES*SP)   // 100352 conv-gemm rows

// ---------------- device scratch (static, no allocs) ----------------
__device__ float g_pooled[(size_t)M_BOXES*C_FEAT*SP];     // 205.5 MB
__device__ float g_partial[(size_t)SPLITK*M_BOXES*HID];   // 16 MB
__device__ float g_h[M_BOXES*HID];
__device__ float g_zsum[M_BOXES*OCONV];
__device__ float g_wt[(size_t)KCONV*OCONV];               // w_conv transposed [k][oc]
__device__ float g_boxp[M_BOXES*8];                       // sx1,sy1,sx2,sy2,lvl,bidx

// ---------------- K1: per-box FPN level + scaled coords ----------------
__global__ void k_prep(const float* __restrict__ boxes,
                       const int* __restrict__ bidx,
                       const int* __restrict__ ph, const int* __restrict__ pw) {
    int m = threadIdx.x;
    if (m >= M_BOXES) return;
    int ih = ph[0], iw = pw[0];
    // tolerate float-encoded scalars
    if (ih <= 0 || ih > 100000) ih = (int)__int_as_float(ph[0]);
    if (iw <= 0 || iw > 100000) iw = (int)__int_as_float(pw[0]);
    float alpha = (224.0f / 800.0f) * (float)min(ih, iw);

    float x1 = boxes[m*4+0], y1 = boxes[m*4+1], x2 = boxes[m*4+2], y2 = boxes[m*4+3];
    float bw = fabsf(x2 - x1), bh = fabsf(y2 - y1);
    float s  = sqrtf(fmaxf(bw*bh, 1e-6f));
    float k  = floorf(4.0f + log2f(s / alpha));
    int lvl  = (int)fminf(fmaxf(k - 2.0f, 0.0f), 3.0f);
    float scale = 1.0f / (float)(4 << lvl);

    g_boxp[m*8+0] = x1*scale;
    g_boxp[m*8+1] = y1*scale;
    g_boxp[m*8+2] = x2*scale;
    g_boxp[m*8+3] = y2*scale;
    g_boxp[m*8+4] = (float)lvl;
    g_boxp[m*8+5] = (float)bidx[m];
}

// ---------------- K2: RoIAlign (1 sample per bin center) ----------------
__global__ void __launch_bounds__(256) k_roi(const float* __restrict__ p2,
                                             const float* __restrict__ p3,
                                             const float* __restrict__ p4,
                                             const float* __restrict__ p5) {
    long long idx = (long long)blockIdx.x * blockDim.x + threadIdx.x;
    const long long total = (long long)M_BOXES * C_FEAT * SP;
    if (idx >= total) return;

    int sidx = (int)(idx % SP);
    int c    = (int)((idx / SP) % C_FEAT);
    int m    = (int)(idx / ((long long)SP * C_FEAT));
    int py = sidx / POOLSZ, px = sidx % POOLSZ;

    const float* bp = &g_boxp[m*8];
    float sx1 = bp[0], sy1 = bp[1], sx2 = bp[2], sy2 = bp[3];
    int lvl = (int)bp[4];
    int bi  = (int)bp[5];

    const float* feat = (lvl == 0) ? p2 : (lvl == 1) ? p3 : (lvl == 2) ? p4 : p5;
    int H = 200 >> lvl;
    int W = H;

    float gx = (px + 0.5f) / (float)POOLSZ;
    float gy = (py + 0.5f) / (float)POOLSZ;
    float xs = sx1 + gx * (sx2 - sx1);
    float ys = sy1 + gy * (sy2 - sy1);
    float x0f = floorf(xs), y0f = floorf(ys);
    float lx = xs - x0f, ly = ys - y0f;
    int ix0 = min(max((int)x0f, 0), W-1);
    int ix1 = min(max((int)x0f + 1, 0), W-1);
    int iy0 = min(max((int)y0f, 0), H-1);
    int iy1 = min(max((int)y0f + 1, 0), H-1);

    const float* base = feat + ((size_t)(bi * C_FEAT + c)) * (size_t)(H * W);
    float v00 = base[iy0*W + ix0];
    float v01 = base[iy0*W + ix1];
    float v10 = base[iy1*W + ix0];
    float v11 = base[iy1*W + ix1];
    float val = v00*(1.f-ly)*(1.f-lx) + v01*(1.f-ly)*lx + v10*ly*(1.f-lx) + v11*ly*lx;
    g_pooled[idx] = val;
}

// ---------------- K3: FC1 GEMM 512x100352x1024, splitK=8 ----------------
// 128x128 tile, BK=8, 256 threads, 8x8 micro-tile
__global__ void __launch_bounds__(256) k_gemm1(const float* __restrict__ B) {
    __shared__ float As[8][128];
    __shared__ float Bs[8][128];
    const float* A = g_pooled;  // [512][100352]

    int tid = threadIdx.x;
    int bn = blockIdx.x, bm = blockIdx.y, sk = blockIdx.z;
    int k0 = sk * KSLICE, kend = k0 + KSLICE;

    int arow = tid >> 1;            // 0..127
    int ak4  = (tid & 1) * 4;       // 0 or 4
    const float* Aptr = A + (size_t)(bm*128 + arow) * KFC + ak4;
    int bk  = tid >> 5;             // 0..7
    int bn4 = (tid & 31) * 4;       // 0..124
    const float* Bptr = B + (size_t)bk * HID + bn*128 + bn4;

    int tx = tid & 15, ty = tid >> 4;
    float acc[8][8];
    #pragma unroll
    for (int i = 0; i < 8; i++)
        #pragma unroll
        for (int j = 0; j < 8; j++) acc[i][j] = 0.f;

    for (int k = k0; k < kend; k += 8) {
        float4 av = *(const float4*)(Aptr + k);
        float4 bv = *(const float4*)(Bptr + (size_t)k * HID);
        __syncthreads();
        As[ak4+0][arow] = av.x;
        As[ak4+1][arow] = av.y;
        As[ak4+2][arow] = av.z;
        As[ak4+3][arow] = av.w;
        *(float4*)&Bs[bk][bn4] = bv;
        __syncthreads();
        #pragma unroll
        for (int kk = 0; kk < 8; kk++) {
            float4 a0 = *(const float4*)&As[kk][ty*8];
            float4 a1 = *(const float4*)&As[kk][ty*8+4];
            float4 b0 = *(const float4*)&Bs[kk][tx*8];
            float4 b1 = *(const float4*)&Bs[kk][tx*8+4];
            float a[8] = {a0.x,a0.y,a0.z,a0.w,a1.x,a1.y,a1.z,a1.w};
            float b[8] = {b0.x,b0.y,b0.z,b0.w,b1.x,b1.y,b1.z,b1.w};
            #pragma unroll
            for (int i = 0; i < 8; i++)
                #pragma unroll
                for (int j = 0; j < 8; j++)
                    acc[i][j] = fmaf(a[i], b[j], acc[i][j]);
        }
    }

    float* P = g_partial + ((size_t)sk * M_BOXES + (size_t)bm*128) * HID + bn*128;
    #pragma unroll
    for (int i = 0; i < 8; i++) {
        size_t ro = (size_t)(ty*8 + i) * HID + tx*8;
        *(float4*)&P[ro]   = make_float4(acc[i][0], acc[i][1], acc[i][2], acc[i][3]);
        *(float4*)&P[ro+4] = make_float4(acc[i][4], acc[i][5], acc[i][6], acc[i][7]);
    }
}

__global__ void k_reduce1(const float* __restrict__ bfc1) {
    int idx = blockIdx.x * blockDim.x + threadIdx.x;
    if (idx >= M_BOXES * HID) return;
    float v = 0.f;
    #pragma unroll
    for (int s = 0; s < SPLITK; s++)
        v += g_partial[(size_t)s * M_BOXES * HID + idx];
    v += bfc1[idx % HID];
    g_h[idx] = fmaxf(v, 0.f);
}

// ---------------- K4: cls/box heads + softmax ----------------
__global__ void __launch_bounds__(128) k_heads(const float* __restrict__ wc,
                                               const float* __restrict__ bc,
                                               const float* __restrict__ wb,
                                               const float* __restrict__ bb,
                                               float* __restrict__ out) {
    __shared__ float hrow[HID];
    __shared__ float lg[NCLS];
    __shared__ float mx, sm;
    int m = blockIdx.x, tid = threadIdx.x;
    for (int k = tid; k < HID; k += blockDim.x) hrow[k] = g_h[m*HID + k];
    __syncthreads();
    if (tid < NCLS) {
        float ac = bc[tid], ab = bb[tid];
        for (int k = 0; k < HID; k++) {
            float h = hrow[k];
            ac = fmaf(h, wc[k*NCLS + tid], ac);
            ab = fmaf(h, wb[k*NCLS + tid], ab);
        }
        lg[tid] = ac;
        out[PART + m*NCLS + tid] = ab;
    }
    __syncthreads();
    if (tid == 0) {
        float v = -1e30f;
        for (int c = 0; c < NCLS; c++) v = fmaxf(v, lg[c]);
        mx = v;
    }
    __syncthreads();
    if (tid < NCLS) lg[tid] = expf(lg[tid] - mx);
    __syncthreads();
    if (tid == 0) {
        float v = 0.f;
        for (int c = 0; c < NCLS; c++) v += lg[c];
        sm = v;
    }
    __syncthreads();
    if (tid < NCLS) out[m*NCLS + tid] = lg[tid] / sm;
}

// ---------------- K5 helpers: weight transpose + zsum zero ----------------
__global__ void k_wt(const float* __restrict__ wconv) {
    int idx = blockIdx.x * blockDim.x + threadIdx.x;
    if (idx >= OCONV * KCONV) return;
    int oc = idx / KCONV, k = idx % KCONV;
    g_wt[(size_t)k * OCONV + oc] = wconv[idx];
}

__global__ void k_zero() {
    int idx = blockIdx.x * blockDim.x + threadIdx.x;
    if (idx < M_BOXES * OCONV) g_zsum[idx] = 0.f;
}

// ---------------- K5: 3x3 conv as implicit-im2col GEMM + fused mean-reduce ----------------
// M'=100352 (box*spatial), K'=4608, N'=256; grid (2 N-tiles, 784 M-tiles)
__global__ void __launch_bounds__(256) k_convgemm(const float* __restrict__ bconv) {
    __shared__ float smem[2048];
    float (*As)[128] = (float (*)[128])smem;
    float (*Bs)[128] = (float (*)[128])(smem + 1024);

    int tid = threadIdx.x;
    int bn = blockIdx.x;                 // 0..1
    int rowbase = blockIdx.y * 128;      // 0..100224

    int arow = tid >> 1;
    int ak4  = (tid & 1) * 4;
    int grow = rowbase + arow;
    int am = grow / SP;
    int asp = grow % SP;
    int ay = asp / POOLSZ, ax = asp % POOLSZ;
    const float* Ain = g_pooled + (size_t)am * C_FEAT * SP;

    int bk  = tid >> 5;
    int bn4 = (tid & 31) * 4;
    const float* Bptr = g_wt + (size_t)bk * OCONV + bn*128 + bn4;

    int tx = tid & 15, ty = tid >> 4;
    float acc[8][8];
    #pragma unroll
    for (int i = 0; i < 8; i++)
        #pragma unroll
        for (int j = 0; j < 8; j++) acc[i][j] = 0.f;

    for (int k0 = 0; k0 < KCONV; k0 += 8) {
        float avals[4];
        #pragma unroll
        for (int kk = 0; kk < 4; kk++) {
            int k  = k0 + ak4 + kk;
            int ic = k / 9;
            int r  = k - ic*9;
            int dy = r / 3 - 1;
            int dx = r - (r/3)*3 - 1;
            int yy = ay + dy, xx = ax + dx;
            avals[kk] = (yy >= 0 && yy < POOLSZ && xx >= 0 && xx < POOLSZ)
                        ? Ain[ic*SP + yy*POOLSZ + xx] : 0.f;
        }
        float4 bv = *(const float4*)(Bptr + (size_t)k0 * OCONV);
        __syncthreads();
        As[ak4+0][arow] = avals[0];
        As[ak4+1][arow] = avals[1];
        As[ak4+2][arow] = avals[2];
        As[ak4+3][arow] = avals[3];
        *(float4*)&Bs[bk][bn4] = bv;
        __syncthreads();
        #pragma unroll
        for (int kk = 0; kk < 8; kk++) {
            float4 a0 = *(const float4*)&As[kk][ty*8];
            float4 a1 = *(const float4*)&As[kk][ty*8+4];
            float4 b0 = *(const float4*)&Bs[kk][tx*8];
            float4 b1 = *(const float4*)&Bs[kk][tx*8+4];
            float a[8] = {a0.x,a0.y,a0.z,a0.w,a1.x,a1.y,a1.z,a1.w};
            float b[8] = {b0.x,b0.y,b0.z,b0.w,b1.x,b1.y,b1.z,b1.w};
            #pragma unroll
            for (int i = 0; i < 8; i++)
                #pragma unroll
                for (int j = 0; j < 8; j++)
                    acc[i][j] = fmaf(a[i], b[j], acc[i][j]);
        }
    }

    // epilogue: z = relu(acc + b), reduce over spatial rows into g_zsum[m][oc]
    int m0 = rowbase / SP;
    int mlast = (rowbase + 127) / SP;   // m0 or m0+1 (196 > 128)
    float s0[8], s1[8];
    #pragma unroll
    for (int j = 0; j < 8; j++) { s0[j] = 0.f; s1[j] = 0.f; }
    #pragma unroll
    for (int i = 0; i < 8; i++) {
        int mi = (rowbase + ty*8 + i) / SP;
        #pragma unroll
        for (int j = 0; j < 8; j++) {
            int oc = bn*128 + tx*8 + j;
            float z = fmaxf(acc[i][j] + bconv[oc], 0.f);
            if (mi == m0) s0[j] += z; else s1[j] += z;
        }
    }
    __syncthreads();
    float* red = smem;  // 16 x 128
    #pragma unroll
    for (int j = 0; j < 8; j++) red[ty*128 + tx*8 + j] = s0[j];
    __syncthreads();
    if (ty == 0) {
        #pragma unroll
        for (int j = 0; j < 8; j++) {
            int col = tx*8 + j;
            float v = 0.f;
            #pragma unroll
            for (int t = 0; t < 16; t++) v += red[t*128 + col];
            atomicAdd(&g_zsum[m0*OCONV + bn*128 + col], v);
        }
    }
    __syncthreads();
    if (mlast != m0) {
        #pragma unroll
        for (int j = 0; j < 8; j++) red[ty*128 + tx*8 + j] = s1[j];
        __syncthreads();
        if (ty == 0) {
            #pragma unroll
            for (int j = 0; j < 8; j++) {
                int col = tx*8 + j;
                float v = 0.f;
                #pragma unroll
                for (int t = 0; t < 16; t++) v += red[t*128 + col];
                atomicAdd(&g_zsum[mlast*OCONV + bn*128 + col], v);
            }
        }
    }
}

// ---------------- K6: mask FC + sigmoid ----------------
__global__ void __launch_bounds__(128) k_maskhead(const float* __restrict__ wm,
                                                  const float* __restrict__ bm_,
                                                  float* __restrict__ out) {
    int m = blockIdx.x, t = threadIdx.x;
    if (t >= NCLS) return;
    float acc = bm_[t];
    for (int oc = 0; oc < OCONV; oc++)
        acc = fmaf(g_zsum[m*OCONV + oc] * (1.0f/196.0f), wm[oc*NCLS + t], acc);
    out[2*PART + m*NCLS + t] = 1.0f / (1.0f + expf(-acc));
}

// ---------------- launch ----------------
extern "C" void kernel_launch(void* const* d_in, const int* in_sizes, int n_in,
                              void* d_out, int out_size) {
    const float* p2     = (const float*)d_in[0];
    const float* p3     = (const float*)d_in[1];
    const float* p4     = (const float*)d_in[2];
    const float* p5     = (const float*)d_in[3];
    const float* boxes  = (const float*)d_in[4];
    const int*   bidx   = (const int*)  d_in[5];
    const float* w_fc1  = (const float*)d_in[6];
    const float* b_fc1  = (const float*)d_in[7];
    const float* w_cls  = (const float*)d_in[8];
    const float* b_cls  = (const float*)d_in[9];
    const float* w_box  = (const float*)d_in[10];
    const float* b_box  = (const float*)d_in[11];
    const float* w_conv = (const float*)d_in[12];
    const float* b_conv = (const float*)d_in[13];
    const float* w_mfc  = (const float*)d_in[14];
    const float* b_mfc  = (const float*)d_in[15];
    const int*   img_h  = (const int*)  d_in[16];
    const int*   img_w  = (const int*)  d_in[17];
    float* out = (float*)d_out;

    k_prep<<<1, 512>>>(boxes, bidx, img_h, img_w);
    k_wt<<<(OCONV*KCONV + 255)/256, 256>>>(w_conv);
    k_zero<<<(M_BOXES*OCONV + 255)/256, 256>>>();

    long long roi_total = (long long)M_BOXES * C_FEAT * SP;
    k_roi<<<(unsigned)((roi_total + 255)/256), 256>>>(p2, p3, p4, p5);

    k_gemm1<<<dim3(HID/128, M_BOXES/128, SPLITK), 256>>>(w_fc1);
    k_reduce1<<<(M_BOXES*HID + 255)/256, 256>>>(b_fc1);
    k_heads<<<M_BOXES, 128>>>(w_cls, b_cls, w_box, b_box, out);

    k_convgemm<<<dim3(OCONV/128, MROWS/128), 256>>>(b_conv);
    k_maskhead<<<M_BOXES, 128>>>(w_mfc, b_mfc, out);
}

// round 9
// speedup vs baseline: 2.1521x; 2.1521x over previous
#include <cuda_runtime.h>
#include <cuda_bf16.h>
#include <math.h>
#include <stdint.h>

#define M_BOXES 512
#define C_FEAT  512
#define POOLSZ  14
#define SP      196
#define HID     1024
#define NCLS    81
#define OCONV   256
#define KFC     100352
#define SPLITK  8
#define KSLICE  (KFC/SPLITK)
#define PART    (M_BOXES*NCLS)
#define MROWS   (M_BOXES*SP)

// smem tile geometry: 128 rows x 8 chunks(16B) data + 1 pad chunk = 144B pitch
#define PITCH   144
#define OPBYTES (128*PITCH)      // 18432 per operand
#define STAGEB  (2*OPBYTES)      // 36864 per stage (A+B)

__device__ float         g_pooled[(size_t)M_BOXES*C_FEAT*SP];
__device__ __nv_bfloat16 g_pA_hi[(size_t)MROWS*C_FEAT];
__device__ __nv_bfloat16 g_pA_lo[(size_t)MROWS*C_FEAT];
__device__ __nv_bfloat16 g_wfc_hi[(size_t)HID*KFC];
__device__ __nv_bfloat16 g_wfc_lo[(size_t)HID*KFC];
__device__ __nv_bfloat16 g_wcv_hi[(size_t)9*OCONV*C_FEAT];
__device__ __nv_bfloat16 g_wcv_lo[(size_t)9*OCONV*C_FEAT];
__device__ float         g_partial[(size_t)SPLITK*M_BOXES*HID];
__device__ float         g_h[M_BOXES*HID];
__device__ float         g_zsum[M_BOXES*OCONV];
__device__ float         g_boxp[M_BOXES*8];

__device__ __forceinline__ uint32_t smem_u32(const void* p){
    uint32_t a; asm("{ .reg .u64 t; cvta.to.shared.u64 t, %1; cvt.u32.u64 %0, t; }":"=r"(a):"l"(p)); return a;
}
__device__ __forceinline__ void cp16(uint32_t dst, const void* src){
    asm volatile("cp.async.ca.shared.global [%0], [%1], 16;"::"r"(dst),"l"(src));
}
__device__ __forceinline__ void cp16z(uint32_t dst, const void* src, int sz){
    asm volatile("cp.async.ca.shared.global [%0], [%1], 16, %2;"::"r"(dst),"l"(src),"r"(sz));
}
__device__ __forceinline__ void cp_commit(){ asm volatile("cp.async.commit_group;":::"memory"); }
template<int N> __device__ __forceinline__ void cp_wait(){
    asm volatile("cp.async.wait_group %0;"::"n"(N):"memory");
}
__device__ __forceinline__ void ldm4(uint32_t* f, uint32_t addr){
    asm volatile("ldmatrix.sync.aligned.m8n8.x4.shared.b16 {%0,%1,%2,%3}, [%4];"
        :"=r"(f[0]),"=r"(f[1]),"=r"(f[2]),"=r"(f[3]):"r"(addr));
}
__device__ __forceinline__ void mma16816(float* c, const uint32_t* a, const uint32_t* b){
    asm volatile("mma.sync.aligned.m16n8k16.row.col.f32.bf16.bf16.f32 "
        "{%0,%1,%2,%3},{%4,%5,%6,%7},{%8,%9},{%0,%1,%2,%3};"
        :"+f"(c[0]),"+f"(c[1]),"+f"(c[2]),"+f"(c[3])
        :"r"(a[0]),"r"(a[1]),"r"(a[2]),"r"(a[3]),"r"(b[0]),"r"(b[1]));
}

// 3-pass (hh, hl, lh) HMMA over one 128x128x32 stage.
// aAddr/bAddr: per-lane ldmatrix bases for this stage.
__device__ __forceinline__ void hmma_tile(uint32_t aAddr, uint32_t bAddr, float acc[16][4]){
    #pragma unroll
    for (int pass=0; pass<3; pass++){
        const int ca = (pass==2)?64:0;   // A lo half byte offset
        const int cb = (pass==1)?64:0;   // B lo half
        #pragma unroll
        for (int s=0; s<2; s++){
            uint32_t af[2][4], bf[4][4];
            ldm4(af[0], aAddr + ca + s*32);
            ldm4(af[1], aAddr + 16*PITCH + ca + s*32);
            #pragma unroll
            for (int p=0;p<4;p++) ldm4(bf[p], bAddr + p*16*PITCH + cb + s*32);
            #pragma unroll
            for (int mi=0;mi<2;mi++)
                #pragma unroll
                for (int ni=0;ni<8;ni++)
                    mma16816(acc[mi*8+ni], af[mi], &bf[ni>>1][(ni&1)*2]);
        }
    }
}

__global__ void k_prep(const float* __restrict__ boxes, const int* __restrict__ bidx,
                       const int* __restrict__ ph, const int* __restrict__ pw){
    int m = threadIdx.x; if (m >= M_BOXES) return;
    int ih = ph[0], iw = pw[0];
    if (ih <= 0 || ih > 100000) ih = (int)__int_as_float(ph[0]);
    if (iw <= 0 || iw > 100000) iw = (int)__int_as_float(pw[0]);
    float alpha = (224.0f/800.0f)*(float)min(ih,iw);
    float x1=boxes[m*4+0], y1=boxes[m*4+1], x2=boxes[m*4+2], y2=boxes[m*4+3];
    float s = sqrtf(fmaxf(fabsf(x2-x1)*fabsf(y2-y1), 1e-6f));
    float k = floorf(4.0f + log2f(s/alpha));
    int lvl = (int)fminf(fmaxf(k-2.0f,0.0f),3.0f);
    float sc = 1.0f/(float)(4<<lvl);
    g_boxp[m*8+0]=x1*sc; g_boxp[m*8+1]=y1*sc; g_boxp[m*8+2]=x2*sc; g_boxp[m*8+3]=y2*sc;
    g_boxp[m*8+4]=(float)lvl; g_boxp[m*8+5]=(float)bidx[m];
}

__global__ void __launch_bounds__(256) k_roi(const float* __restrict__ p2, const float* __restrict__ p3,
                                             const float* __restrict__ p4, const float* __restrict__ p5){
    long long idx = (long long)blockIdx.x*blockDim.x + threadIdx.x;
    if (idx >= (long long)M_BOXES*C_FEAT*SP) return;
    int sidx = (int)(idx % SP);
    int c    = (int)((idx / SP) % C_FEAT);
    int m    = (int)(idx / ((long long)SP*C_FEAT));
    int py = sidx/POOLSZ, px = sidx%POOLSZ;
    const float* bp = &g_boxp[m*8];
    int lvl = (int)bp[4], bi = (int)bp[5];
    const float* feat = (lvl==0)?p2:(lvl==1)?p3:(lvl==2)?p4:p5;
    int H = 200>>lvl, W = H;
    float xs = bp[0] + (px+0.5f)/POOLSZ*(bp[2]-bp[0]);
    float ys = bp[1] + (py+0.5f)/POOLSZ*(bp[3]-bp[1]);
    float x0f = floorf(xs), y0f = floorf(ys);
    float lx = xs-x0f, ly = ys-y0f;
    int ix0 = min(max((int)x0f,0),W-1), ix1 = min(max((int)x0f+1,0),W-1);
    int iy0 = min(max((int)y0f,0),H-1), iy1 = min(max((int)y0f+1,0),H-1);
    const float* base = feat + ((size_t)(bi*C_FEAT+c))*(size_t)(H*W);
    float v00=base[iy0*W+ix0], v01=base[iy0*W+ix1], v10=base[iy1*W+ix0], v11=base[iy1*W+ix1];
    g_pooled[idx] = v00*(1.f-ly)*(1.f-lx)+v01*(1.f-ly)*lx+v10*ly*(1.f-lx)+v11*ly*lx;
}

// pooled [m][c][sp] f32 -> [m][sp][c] bf16 hi/lo
__global__ void __launch_bounds__(256) k_patrans(){
    __shared__ float s[32][33];
    int m = blockIdx.z, c0 = blockIdx.y*32, sp0 = blockIdx.x*32;
    int tx = threadIdx.x, ty = threadIdx.y;
    #pragma unroll
    for (int i=0;i<4;i++){
        int cl = ty+i*8, sp = sp0+tx;
        s[cl][tx] = (sp<SP) ? g_pooled[((size_t)m*C_FEAT+c0+cl)*SP+sp] : 0.f;
    }
    __syncthreads();
    #pragma unroll
    for (int i=0;i<4;i++){
        int spl = ty+i*8, sp = sp0+spl;
        if (sp<SP){
            float v = s[tx][spl];
            __nv_bfloat16 h = __float2bfloat16(v);
            size_t o = ((size_t)m*SP+sp)*C_FEAT+c0+tx;
            g_pA_hi[o]=h; g_pA_lo[o]=__float2bfloat16(v-__bfloat162float(h));
        }
    }
}

// w_fc1 [c*196+sp][n] -> [n][sp*512+c] hi/lo
__global__ void __launch_bounds__(256) k_wfct(const float* __restrict__ w){
    __shared__ float s[32][33];
    int sp = blockIdx.z, c0 = blockIdx.y*32, n0 = blockIdx.x*32;
    int tx = threadIdx.x, ty = threadIdx.y;
    #pragma unroll
    for (int i=0;i<4;i++){
        int cl = ty+i*8;
        s[cl][tx] = w[((size_t)(c0+cl)*SP+sp)*HID + n0+tx];
    }
    __syncthreads();
    #pragma unroll
    for (int i=0;i<4;i++){
        int nl = ty+i*8;
        float v = s[tx][nl];
        __nv_bfloat16 h = __float2bfloat16(v);
        size_t o = (size_t)(n0+nl)*KFC + (size_t)sp*C_FEAT + c0+tx;
        g_wfc_hi[o]=h; g_wfc_lo[o]=__float2bfloat16(v-__bfloat162float(h));
    }
}

// w_conv OIHW -> [r][oc][ic] hi/lo
__global__ void k_wcvt(const float* __restrict__ w){
    int idx = blockIdx.x*blockDim.x + threadIdx.x;
    if (idx >= 9*OCONV*C_FEAT) return;
    int r = idx/(OCONV*C_FEAT), rm = idx%(OCONV*C_FEAT);
    int oc = rm/C_FEAT, ic = rm%C_FEAT;
    float v = w[(size_t)oc*4608 + ic*9 + r];
    __nv_bfloat16 h = __float2bfloat16(v);
    g_wcv_hi[idx]=h; g_wcv_lo[idx]=__float2bfloat16(v-__bfloat162float(h));
}

__global__ void k_zero(){
    int i = blockIdx.x*blockDim.x + threadIdx.x;
    if (i < M_BOXES*OCONV) g_zsum[i]=0.f;
}

// ---------------- FC1 HMMA GEMM: grid (8 n, 4 m, 8 splitK) ----------------
__global__ void __launch_bounds__(256,2) k_mm1(){
    extern __shared__ __align__(16) char dynsm[];
    uint32_t sbase = smem_u32(dynsm);
    int tid = threadIdx.x, wid = tid>>5, L = tid&31;
    int widm = wid&3, widn = wid>>2;
    int bn = blockIdx.x, bm = blockIdx.y, sk = blockIdx.z;
    int rw = tid>>1, t1 = tid&1;
    int k0b = sk*KSLICE;
    const int nIter = KSLICE/32;   // 392

    const __nv_bfloat16* Asrc = (t1 ? g_pA_lo  : g_pA_hi)  + (size_t)(bm*128+rw)*KFC;
    const __nv_bfloat16* Bsrc = (t1 ? g_wfc_lo : g_wfc_hi) + (size_t)(bn*128+rw)*KFC;
    uint32_t ld_a = sbase + rw*PITCH + t1*64;
    uint32_t ld_b = ld_a + OPBYTES;

    // per-lane ldmatrix bases (stage 0)
    uint32_t aA = sbase + (widm*32 + (L&7) + 8*((L>>3)&1))*PITCH + (L>>4)*16;
    uint32_t aB = sbase + OPBYTES + (widn*64 + (L&7) + 8*(L>>4))*PITCH + ((L>>3)&1)*16;

    float acc[16][4];
    #pragma unroll
    for (int i=0;i<16;i++){ acc[i][0]=0.f; acc[i][1]=0.f; acc[i][2]=0.f; acc[i][3]=0.f; }

#define FC_LD(ST,IT) do { \
        int kb_ = k0b + (IT)*32; \
        uint32_t off_ = (ST)*STAGEB; \
        _Pragma("unroll") \
        for (int j=0;j<4;j++) cp16(ld_a + off_ + j*16, Asrc + kb_ + j*8); \
        _Pragma("unroll") \
        for (int j=0;j<4;j++) cp16(ld_b + off_ + j*16, Bsrc + kb_ + j*8); \
        cp_commit(); } while(0)

    FC_LD(0,0);
    for (int it=0; it<nIter; ++it){
        if (it+1 < nIter){ FC_LD((it+1)&1, it+1); cp_wait<1>(); }
        else cp_wait<0>();
        __syncthreads();
        uint32_t off = (it&1)*STAGEB;
        hmma_tile(aA + off, aB + off, acc);
        __syncthreads();
    }
#undef FC_LD

    // store to g_partial
    #pragma unroll
    for (int mi=0;mi<2;mi++)
        #pragma unroll
        for (int ni=0;ni<8;ni++)
            #pragma unroll
            for (int cq=0;cq<4;cq++){
                int row = bm*128 + widm*32 + mi*16 + (L>>2) + 8*(cq>>1);
                int col = bn*128 + widn*64 + ni*8 + 2*(L&3) + (cq&1);
                g_partial[((size_t)sk*M_BOXES + row)*HID + col] = acc[mi*8+ni][cq];
            }
}

__global__ void k_reduce1(const float* __restrict__ bfc1){
    int idx = blockIdx.x*blockDim.x + threadIdx.x;
    if (idx >= M_BOXES*HID) return;
    float v = 0.f;
    #pragma unroll
    for (int s=0;s<SPLITK;s++) v += g_partial[(size_t)s*M_BOXES*HID + idx];
    g_h[idx] = fmaxf(v + bfc1[idx%HID], 0.f);
}

__global__ void __launch_bounds__(128) k_heads(const float* __restrict__ wc, const float* __restrict__ bc,
                                               const float* __restrict__ wb, const float* __restrict__ bb,
                                               float* __restrict__ out){
    __shared__ float hrow[HID];
    __shared__ float lg[NCLS];
    __shared__ float mx, sm;
    int m = blockIdx.x, tid = threadIdx.x;
    for (int k=tid;k<HID;k+=blockDim.x) hrow[k] = g_h[m*HID+k];
    __syncthreads();
    if (tid<NCLS){
        float ac = bc[tid], ab = bb[tid];
        for (int k=0;k<HID;k++){
            float h = hrow[k];
            ac = fmaf(h, wc[k*NCLS+tid], ac);
            ab = fmaf(h, wb[k*NCLS+tid], ab);
        }
        lg[tid]=ac;
        out[PART + m*NCLS + tid] = ab;
    }
    __syncthreads();
    if (tid==0){ float v=-1e30f; for(int c=0;c<NCLS;c++) v=fmaxf(v,lg[c]); mx=v; }
    __syncthreads();
    if (tid<NCLS) lg[tid] = expf(lg[tid]-mx);
    __syncthreads();
    if (tid==0){ float v=0.f; for(int c=0;c<NCLS;c++) v+=lg[c]; sm=v; }
    __syncthreads();
    if (tid<NCLS) out[m*NCLS+tid] = lg[tid]/sm;
}

// ---------------- conv HMMA: 9 shifted taps in K; grid (2 n, 784 m) ----------------
__global__ void __launch_bounds__(256,2) k_mm2(const float* __restrict__ bconv){
    extern __shared__ __align__(16) char dynsm[];
    uint32_t sbase = smem_u32(dynsm);
    int tid = threadIdx.x, wid = tid>>5, L = tid&31;
    int widm = wid&3, widn = wid>>2;
    int nbase = blockIdx.x*128;
    int rowbase = blockIdx.y*128;
    int rw = tid>>1, t1 = tid&1;
    const int nIter = 144;  // 9 taps * 16

    int grow = rowbase + rw;
    int am = grow/SP;
    int asp = grow - am*SP;
    int ay = asp/POOLSZ, ax = asp - ay*POOLSZ;
    const __nv_bfloat16* Abase0 = (t1 ? g_pA_lo : g_pA_hi) + (size_t)am*SP*C_FEAT;
    const __nv_bfloat16* Bsrc0  = (t1 ? g_wcv_lo : g_wcv_hi);
    uint32_t ld_a = sbase + rw*PITCH + t1*64;
    uint32_t ld_b = ld_a + OPBYTES;

    uint32_t aA = sbase + (widm*32 + (L&7) + 8*((L>>3)&1))*PITCH + (L>>4)*16;
    uint32_t aB = sbase + OPBYTES + (widn*64 + (L&7) + 8*(L>>4))*PITCH + ((L>>3)&1)*16;

    float acc[16][4];
    #pragma unroll
    for (int i=0;i<16;i++){ acc[i][0]=0.f; acc[i][1]=0.f; acc[i][2]=0.f; acc[i][3]=0.f; }

#define CV_LD(ST,IT) do { \
        int r_ = (IT)>>4, kk_ = ((IT)&15)*32; \
        int dy_ = r_/3 - 1, dx_ = r_ - (r_/3)*3 - 1; \
        int yy_ = ay+dy_, xx_ = ax+dx_; \
        int ok_ = (((unsigned)yy_ < (unsigned)POOLSZ) && ((unsigned)xx_ < (unsigned)POOLSZ)) ? 16 : 0; \
        const __nv_bfloat16* as_ = Abase0 + (size_t)(ok_ ? (yy_*POOLSZ+xx_) : 0)*C_FEAT + kk_; \
        const __nv_bfloat16* bs_ = Bsrc0 + ((size_t)r_*OCONV + nbase + rw)*C_FEAT + kk_; \
        uint32_t off_ = (ST)*STAGEB; \
        _Pragma("unroll") \
        for (int j=0;j<4;j++) cp16z(ld_a + off_ + j*16, as_ + j*8, ok_); \
        _Pragma("unroll") \
        for (int j=0;j<4;j++) cp16(ld_b + off_ + j*16, bs_ + j*8); \
        cp_commit(); } while(0)

    CV_LD(0,0);
    for (int it=0; it<nIter; ++it){
        if (it+1 < nIter){ CV_LD((it+1)&1, it+1); cp_wait<1>(); }
        else cp_wait<0>();
        __syncthreads();
        uint32_t off = (it&1)*STAGEB;
        hmma_tile(aA + off, aB + off, acc);
        __syncthreads();
    }
#undef CV_LD

    // epilogue: bias+relu, xor-shuffle reduce 8 rows, atomicAdd per box
    #pragma unroll
    for (int mi=0;mi<2;mi++)
        #pragma unroll
        for (int cq2=0;cq2<2;cq2++){
            int rbase = rowbase + widm*32 + mi*16 + 8*cq2;   // rows rbase..rbase+7
            int b0 = rbase/SP, b1 = (rbase+7)/SP;
            int mybox = (rbase + (L>>2))/SP;
            #pragma unroll
            for (int ni=0;ni<8;ni++)
                #pragma unroll
                for (int q=0;q<2;q++){
                    int cq = cq2*2 + q;
                    int col = nbase + widn*64 + ni*8 + 2*(L&3) + q;
                    float z = fmaxf(acc[mi*8+ni][cq] + __ldg(&bconv[col]), 0.f);
                    float z0 = (mybox==b0) ? z : 0.f;
                    z0 += __shfl_xor_sync(0xffffffffu, z0, 4);
                    z0 += __shfl_xor_sync(0xffffffffu, z0, 8);
                    z0 += __shfl_xor_sync(0xffffffffu, z0, 16);
                    if ((L>>2)==0) atomicAdd(&g_zsum[b0*OCONV+col], z0);
                    if (b1 != b0){
                        float z1 = (mybox==b1) ? z : 0.f;
                        z1 += __shfl_xor_sync(0xffffffffu, z1, 4);
                        z1 += __shfl_xor_sync(0xffffffffu, z1, 8);
                        z1 += __shfl_xor_sync(0xffffffffu, z1, 16);
                        if ((L>>2)==0) atomicAdd(&g_zsum[b1*OCONV+col], z1);
                    }
                }
        }
}

__global__ void __launch_bounds__(128) k_maskhead(const float* __restrict__ wm,
                                                  const float* __restrict__ bm_,
                                                  float* __restrict__ out){
    int m = blockIdx.x, t = threadIdx.x;
    if (t >= NCLS) return;
    float acc = bm_[t];
    for (int oc=0; oc<OCONV; oc++)
        acc = fmaf(g_zsum[m*OCONV+oc]*(1.0f/196.0f), wm[oc*NCLS+t], acc);
    out[2*PART + m*NCLS + t] = 1.0f/(1.0f + expf(-acc));
}

extern "C" void kernel_launch(void* const* d_in, const int* in_sizes, int n_in,
                              void* d_out, int out_size){
    const float* p2     = (const float*)d_in[0];
    const float* p3     = (const float*)d_in[1];
    const float* p4     = (const float*)d_in[2];
    const float* p5     = (const float*)d_in[3];
    const float* boxes  = (const float*)d_in[4];
    const int*   bidx   = (const int*)  d_in[5];
    const float* w_fc1  = (const float*)d_in[6];
    const float* b_fc1  = (const float*)d_in[7];
    const float* w_cls  = (const float*)d_in[8];
    const float* b_cls  = (const float*)d_in[9];
    const float* w_box  = (const float*)d_in[10];
    const float* b_box  = (const float*)d_in[11];
    const float* w_conv = (const float*)d_in[12];
    const float* b_conv = (const float*)d_in[13];
    const float* w_mfc  = (const float*)d_in[14];
    const float* b_mfc  = (const float*)d_in[15];
    const int*   img_h  = (const int*)  d_in[16];
    const int*   img_w  = (const int*)  d_in[17];
    float* out = (float*)d_out;

    cudaFuncSetAttribute(k_mm1, cudaFuncAttributeMaxDynamicSharedMemorySize, 2*STAGEB);
    cudaFuncSetAttribute(k_mm2, cudaFuncAttributeMaxDynamicSharedMemorySize, 2*STAGEB);

    k_prep<<<1, 512>>>(boxes, bidx, img_h, img_w);
    k_wcvt<<<(9*OCONV*C_FEAT + 255)/256, 256>>>(w_conv);
    k_zero<<<(M_BOXES*OCONV + 255)/256, 256>>>();

    long long roi_total = (long long)M_BOXES*C_FEAT*SP;
    k_roi<<<(unsigned)((roi_total + 255)/256), 256>>>(p2, p3, p4, p5);
    k_patrans<<<dim3(7, 16, 512), dim3(32, 8)>>>();
    k_wfct<<<dim3(32, 16, 196), dim3(32, 8)>>>(w_fc1);

    k_mm1<<<dim3(8, 4, 8), 256, 2*STAGEB>>>();
    k_reduce1<<<(M_BOXES*HID + 255)/256, 256>>>(b_fc1);
    k_heads<<<M_BOXES, 128>>>(w_cls, b_cls, w_box, b_box, out);

    k_mm2<<<dim3(2, 784), 256, 2*STAGEB>>>(b_conv);
    k_maskhead<<<M_BOXES, 128>>>(w_mfc, b_mfc, out);
}